// round 12
// baseline (speedup 1.0000x reference)
#include <cuda_runtime.h>
#include <cuda_bf16.h>
#include <cstdint>

// Problem constants
#define BB 4
#define SS 2048
#define DD 1024
#define HH 1024

// Scratch (device globals; no allocation allowed)
__device__ int8_t g_x [(size_t)BB * SS * DD];
__device__ int8_t g_wq[(size_t)HH * DD];
__device__ int8_t g_wk[(size_t)HH * DD];
__device__ int8_t g_wv[(size_t)HH * DD];
__device__ int8_t g_wo[(size_t)HH * HH];
__device__ int8_t g_q[(size_t)BB * SS * HH];
__device__ int8_t g_k[(size_t)BB * SS * HH];
__device__ int8_t g_v[(size_t)BB * SS * HH];
__device__ int8_t g_vT[(size_t)BB * SS * HH];
__device__ int8_t g_attn[(size_t)BB * SS * SS];
__device__ int8_t g_attnq[(size_t)BB * SS * SS];
__device__ int8_t g_ao[(size_t)BB * SS * HH];
__device__ int g_is32;

// ----------------------------------------------------------------------------
// dtype probe + pack (inputs are int32-materialized int8; probe keeps us safe)
// ----------------------------------------------------------------------------
__global__ void detect32(const int* __restrict__ p, int nprobe) {
    __shared__ int bad;
    if (threadIdx.x == 0) bad = 0;
    __syncthreads();
    for (int i = threadIdx.x; i < nprobe; i += blockDim.x) {
        int v = p[i];
        if (v < -300 || v > 300) bad = 1;
    }
    __syncthreads();
    if (threadIdx.x == 0) g_is32 = bad ? 0 : 1;
}

__global__ void pack_s8(const void* __restrict__ in, int8_t* __restrict__ out,
                        long long n4) {
    long long i = (long long)blockIdx.x * blockDim.x + threadIdx.x;
    if (i >= n4) return;
    char4 w;
    if (g_is32) {
        int4 v = ((const int4*)in)[i];
        w.x = (char)v.x; w.y = (char)v.y; w.z = (char)v.z; w.w = (char)v.w;
    } else {
        w = ((const char4*)in)[i];
    }
    ((char4*)out)[i] = w;
}

// ----------------------------------------------------------------------------
// PTX helpers
// ----------------------------------------------------------------------------
__device__ __forceinline__ void cpasync16(uint32_t saddr, const void* gaddr) {
    asm volatile("cp.async.cg.shared.global [%0], [%1], 16;\n"
                 :: "r"(saddr), "l"(gaddr) : "memory");
}

__device__ __forceinline__ void ldsm4(uint32_t& r0, uint32_t& r1, uint32_t& r2,
                                      uint32_t& r3, uint32_t addr) {
    asm volatile("ldmatrix.sync.aligned.m8n8.x4.shared.b16 {%0,%1,%2,%3}, [%4];\n"
                 : "=r"(r0), "=r"(r1), "=r"(r2), "=r"(r3) : "r"(addr));
}

__device__ __forceinline__ void mma_s8(int* c, uint32_t a0, uint32_t a1,
                                       uint32_t a2, uint32_t a3,
                                       uint32_t b0, uint32_t b1) {
    asm volatile(
        "mma.sync.aligned.m16n8k32.row.col.s32.s8.s8.s32 "
        "{%0,%1,%2,%3}, {%4,%5,%6,%7}, {%8,%9}, {%0,%1,%2,%3};\n"
        : "+r"(c[0]), "+r"(c[1]), "+r"(c[2]), "+r"(c[3])
        : "r"(a0), "r"(a1), "r"(a2), "r"(a3), "r"(b0), "r"(b1));
}

__device__ __forceinline__ int quant8(int acc, float s) {
    float f = rintf((float)acc * s);          // round-half-even == jnp.round
    f = fminf(fmaxf(f, -128.0f), 127.0f);
    return (int)f;
}

// ----------------------------------------------------------------------------
// int8 NT GEMM:  C[m,n] = sum_k A[m,k] * B[n,k], requant epilogue
//   Tiles: 128x128x64, 256 threads (8 warps: 2x4 grid of 64x32 warp tiles)
//   epi==0 : int8 out, scale s
//   epi==1 : FLOAT32 out = float(bf16_round(quant * deq))   [harness buffer!]
//   if sxp != nullptr:  s = (*sxp) * cA / cB ; else s = cA
// ----------------------------------------------------------------------------
#define BM 128
#define BN 128
#define BK 64
#define STAGE_BYTES (BM * BK + BN * BK)   // 16384

__global__ void __launch_bounds__(256)
gemm_s8_nt(const int8_t* __restrict__ A, const int8_t* __restrict__ B,
           void* __restrict__ C,
           int M, int N, int K,
           long long sA, long long sB, long long sC,
           float cA, float cB, const float* __restrict__ sxp,
           int epi, float deq)
{
    __shared__ int8_t smem[2][STAGE_BYTES];

    const int tid  = threadIdx.x;
    const int lane = tid & 31;
    const int wid  = tid >> 5;
    const int wm   = wid & 1;    // 2 warps over M
    const int wn   = wid >> 1;   // 4 warps over N

    const long long bz = blockIdx.z;
    const int8_t* Ab = A + bz * sA + (long long)blockIdx.y * BM * K;
    const int8_t* Bb = B + bz * sB + (long long)blockIdx.x * BN * K;

    uint32_t sbase = (uint32_t)__cvta_generic_to_shared(&smem[0][0]);

    const int ntile = K / BK;

    // swizzle: phys 16B chunk = logical chunk ^ ((row>>1)&3)  (rows are 64B)
    auto issue = [&](int kt, int bufsel) {
        uint32_t sa = sbase + bufsel * STAGE_BYTES;
        uint32_t sb = sa + BM * BK;
        #pragma unroll
        for (int i = 0; i < 2; i++) {
            int c  = tid + i * 256;          // 512 chunks of 16B per tile
            int r  = c >> 2;
            int ch = c & 3;
            uint32_t off = r * 64 + ((ch ^ ((r >> 1) & 3)) << 4);
            cpasync16(sa + off, Ab + (long long)r * K + (long long)kt * 64 + ch * 16);
        }
        #pragma unroll
        for (int i = 0; i < 2; i++) {
            int c  = tid + i * 256;
            int r  = c >> 2;
            int ch = c & 3;
            uint32_t off = r * 64 + ((ch ^ ((r >> 1) & 3)) << 4);
            cpasync16(sb + off, Bb + (long long)r * K + (long long)kt * 64 + ch * 16);
        }
        asm volatile("cp.async.commit_group;\n" ::: "memory");
    };

    int acc[4][4][4];
    #pragma unroll
    for (int a = 0; a < 4; a++)
        #pragma unroll
        for (int b = 0; b < 4; b++)
            #pragma unroll
            for (int c = 0; c < 4; c++) acc[a][b][c] = 0;

    issue(0, 0);

    for (int t = 0; t < ntile; t++) {
        if (t + 1 < ntile) {
            issue(t + 1, (t + 1) & 1);
            asm volatile("cp.async.wait_group 1;\n" ::: "memory");
        } else {
            asm volatile("cp.async.wait_group 0;\n" ::: "memory");
        }
        __syncthreads();

        uint32_t sa = sbase + (t & 1) * STAGE_BYTES;
        uint32_t sb = sa + BM * BK;

        #pragma unroll
        for (int ks = 0; ks < 2; ks++) {
            uint32_t afr[4][4], bfr[4][2];
            #pragma unroll
            for (int mi = 0; mi < 4; mi++) {
                int r  = wm * 64 + mi * 16 + (lane & 7) + ((lane >> 3) & 1) * 8;
                int ch = ks * 2 + (lane >> 4);
                ldsm4(afr[mi][0], afr[mi][1], afr[mi][2], afr[mi][3],
                      sa + r * 64 + ((ch ^ ((r >> 1) & 3)) << 4));
            }
            #pragma unroll
            for (int jp = 0; jp < 2; jp++) {
                int r  = wn * 32 + jp * 16 + (lane & 7) + ((lane >> 4) << 3);
                int ch = ks * 2 + ((lane >> 3) & 1);
                uint32_t m0, m1, m2, m3;
                ldsm4(m0, m1, m2, m3,
                      sb + r * 64 + ((ch ^ ((r >> 1) & 3)) << 4));
                bfr[2 * jp][0] = m0; bfr[2 * jp][1] = m1;
                bfr[2 * jp + 1][0] = m2; bfr[2 * jp + 1][1] = m3;
            }
            #pragma unroll
            for (int mi = 0; mi < 4; mi++)
                #pragma unroll
                for (int ni = 0; ni < 4; ni++)
                    mma_s8(acc[mi][ni], afr[mi][0], afr[mi][1], afr[mi][2],
                           afr[mi][3], bfr[ni][0], bfr[ni][1]);
        }
        __syncthreads();
    }

    float s = sxp ? (__ldg(sxp) * cA / cB) : cA;

    const int rowb = blockIdx.y * BM + wm * 64;
    const int colb = blockIdx.x * BN + wn * 32;
    const long long Cbase = bz * sC;

    if (epi == 0) {
        int8_t* Co = (int8_t*)C + Cbase;
        #pragma unroll
        for (int mi = 0; mi < 4; mi++)
            #pragma unroll
            for (int ni = 0; ni < 4; ni++) {
                int r = rowb + mi * 16 + (lane >> 2);
                int c = colb + ni * 8 + (lane & 3) * 2;
                #pragma unroll
                for (int h = 0; h < 2; h++) {
                    int rr = r + h * 8;
                    char2 w;
                    w.x = (char)quant8(acc[mi][ni][2 * h], s);
                    w.y = (char)quant8(acc[mi][ni][2 * h + 1], s);
                    *(char2*)(Co + (size_t)rr * N + c) = w;
                }
            }
    } else {
        // FLOAT32 output buffer; values bf16-rounded to match reference bits
        float* Co = (float*)C + Cbase;
        #pragma unroll
        for (int mi = 0; mi < 4; mi++)
            #pragma unroll
            for (int ni = 0; ni < 4; ni++) {
                int r = rowb + mi * 16 + (lane >> 2);
                int c = colb + ni * 8 + (lane & 3) * 2;
                #pragma unroll
                for (int h = 0; h < 2; h++) {
                    int rr = r + h * 8;
                    float2 w;
                    w.x = __bfloat162float(__float2bfloat16(
                              (float)quant8(acc[mi][ni][2 * h], s) * deq));
                    w.y = __bfloat162float(__float2bfloat16(
                              (float)quant8(acc[mi][ni][2 * h + 1], s) * deq));
                    *(float2*)(Co + (size_t)rr * N + c) = w;
                }
            }
    }
}

// ----------------------------------------------------------------------------
// Softmax + requant over rows of [B*S, S=2048] int8 logits
// ----------------------------------------------------------------------------
__global__ void __launch_bounds__(256)
softmax_rq(const int8_t* __restrict__ a, int8_t* __restrict__ o,
           float scale, float sm_out)
{
    __shared__ float redm[8];
    __shared__ float reds[8];

    const long long row = blockIdx.x;
    const int tid = threadIdx.x;
    const int wid = tid >> 5;

    int2 d = ((const int2*)(a + row * SS))[tid];
    signed char* p = (signed char*)&d;

    float v[8];
    float m = -1e30f;
    #pragma unroll
    for (int i = 0; i < 8; i++) {
        v[i] = (float)p[i] * scale;
        m = fmaxf(m, v[i]);
    }
    #pragma unroll
    for (int s = 16; s; s >>= 1) m = fmaxf(m, __shfl_xor_sync(~0u, m, s));
    if ((tid & 31) == 0) redm[wid] = m;
    __syncthreads();
    if (tid < 32) {
        float t = (tid < 8) ? redm[tid] : -1e30f;
        #pragma unroll
        for (int s = 4; s; s >>= 1) t = fmaxf(t, __shfl_xor_sync(~0u, t, s));
        if (tid == 0) redm[0] = t;
    }
    __syncthreads();
    m = redm[0];

    float e[8];
    float sum = 0.0f;
    #pragma unroll
    for (int i = 0; i < 8; i++) {
        e[i] = expf(v[i] - m);
        sum += e[i];
    }
    #pragma unroll
    for (int s = 16; s; s >>= 1) sum += __shfl_xor_sync(~0u, sum, s);
    if ((tid & 31) == 0) reds[wid] = sum;
    __syncthreads();
    if (tid < 32) {
        float t = (tid < 8) ? reds[tid] : 0.0f;
        #pragma unroll
        for (int s = 4; s; s >>= 1) t += __shfl_xor_sync(~0u, t, s);
        if (tid == 0) reds[0] = t;
    }
    __syncthreads();
    sum = reds[0];

    int2 out;
    signed char* po = (signed char*)&out;
    #pragma unroll
    for (int i = 0; i < 8; i++) {
        float pr = e[i] / sum;
        float f = rintf(pr / sm_out);
        f = fminf(fmaxf(f, -128.0f), 127.0f);
        po[i] = (signed char)(int)f;
    }
    ((int2*)(o + row * SS))[tid] = out;
}

// ----------------------------------------------------------------------------
// int8 transpose per batch:  out[b][h][s] = in[b][s][h]
// ----------------------------------------------------------------------------
__global__ void __launch_bounds__(256)
transpose8(const int8_t* __restrict__ in, int8_t* __restrict__ out)
{
    __shared__ char tile[32][33];
    const long long b = blockIdx.z;
    const int x0 = blockIdx.x * 32;  // H
    const int y0 = blockIdx.y * 32;  // S
    const int8_t* ib = in + b * (long long)SS * HH;
    int8_t* ob = out + b * (long long)HH * SS;

    for (int i = threadIdx.y; i < 32; i += 8)
        tile[i][threadIdx.x] = ib[(size_t)(y0 + i) * HH + x0 + threadIdx.x];
    __syncthreads();
    for (int i = threadIdx.y; i < 32; i += 8)
        ob[(size_t)(x0 + i) * SS + y0 + threadIdx.x] = tile[threadIdx.x][i];
}

// ----------------------------------------------------------------------------
// Launch — inputs identified by ELEMENT COUNT (x: 8388608, weights: 4x1048576
// in relative order, scale_x: 1), falling back to positional.
// ----------------------------------------------------------------------------
extern "C" void kernel_launch(void* const* d_in, const int* in_sizes, int n_in,
                              void* d_out, int out_size)
{
    const void* x_raw = nullptr;
    const void* w_raw[4] = {nullptr, nullptr, nullptr, nullptr};
    const float* sx = nullptr;
    int nw = 0;
    for (int i = 0; i < n_in; i++) {
        long long sz = in_sizes[i];
        if (sz == (long long)BB * SS * DD)       x_raw = d_in[i];
        else if (sz == (long long)HH * DD) {     if (nw < 4) w_raw[nw++] = d_in[i]; }
        else if (sz == 1)                        sx = (const float*)d_in[i];
    }
    if (!x_raw || !sx || nw != 4) {
        x_raw = d_in[0]; sx = (const float*)d_in[1];
        w_raw[0] = d_in[2]; w_raw[1] = d_in[3]; w_raw[2] = d_in[4]; w_raw[3] = d_in[5];
    }

    static int8_t *x = nullptr, *wq, *wk, *wv, *wo,
                  *q, *k, *v, *vT, *attn, *attnq, *ao;
    if (!x) {  // resolved on first (non-captured) correctness call
        cudaGetSymbolAddress((void**)&x,  g_x);
        cudaGetSymbolAddress((void**)&wq, g_wq);
        cudaGetSymbolAddress((void**)&wk, g_wk);
        cudaGetSymbolAddress((void**)&wv, g_wv);
        cudaGetSymbolAddress((void**)&wo, g_wo);
        cudaGetSymbolAddress((void**)&q, g_q);
        cudaGetSymbolAddress((void**)&k, g_k);
        cudaGetSymbolAddress((void**)&v, g_v);
        cudaGetSymbolAddress((void**)&vT, g_vT);
        cudaGetSymbolAddress((void**)&attn, g_attn);
        cudaGetSymbolAddress((void**)&attnq, g_attnq);
        cudaGetSymbolAddress((void**)&ao, g_ao);
    }

    const float c_attn = (float)(0.2 * 0.2);                              // OS_Q*OS_K
    const float c_ao   = (float)((1.0 / 127.0) * 0.74);                   // SM_OUT*OS_V
    const float c_out  = (float)((1.0 / 127.0) * 0.74 * 0.01 / 0.046);    // ... *WS_O/OS_O
    const float smoutf = (float)(1.0 / 127.0);
    const float deq    = 0.046f;                                          // OS_O

    dim3 blk(256);

    // per-tensor dtype probe + pack to int8 scratch
    {
        long long nx = (long long)BB * SS * DD / 4;   // char4 count
        long long nwc = (long long)HH * DD / 4;
        int8_t* wdst[4] = {wq, wk, wv, wo};
        detect32<<<1, 256>>>((const int*)x_raw, 4096);
        pack_s8<<<(unsigned)((nx + 255) / 256), blk>>>(x_raw, x, nx);
        for (int i = 0; i < 4; i++) {
            detect32<<<1, 256>>>((const int*)w_raw[i], 4096);
            pack_s8<<<(unsigned)((nwc + 255) / 256), blk>>>(w_raw[i], wdst[i], nwc);
        }
    }

    // QKV projections: [8192,1024] = X[8192,1024] @ W^T
    {
        dim3 grid(HH / BN, (BB * SS) / BM, 1);
        gemm_s8_nt<<<grid, blk>>>(x, wq, q, BB * SS, HH, DD, 0, 0, 0,
                                  0.0011f, 0.2f, sx, 0, 0.0f);
        gemm_s8_nt<<<grid, blk>>>(x, wk, k, BB * SS, HH, DD, 0, 0, 0,
                                  0.0011f, 0.2f, sx, 0, 0.0f);
        gemm_s8_nt<<<grid, blk>>>(x, wv, v, BB * SS, HH, DD, 0, 0, 0,
                                  0.034f, 0.74f, sx, 0, 0.0f);
    }

    // attn = q @ k^T per batch : [2048,2048], K=1024
    {
        dim3 grid(SS / BN, SS / BM, BB);
        gemm_s8_nt<<<grid, blk>>>(q, k, attn, SS, SS, HH,
                                  (long long)SS * HH, (long long)SS * HH,
                                  (long long)SS * SS,
                                  c_attn, 1.0f, nullptr, 0, 0.0f);
    }

    // softmax + requant
    softmax_rq<<<BB * SS, blk>>>(attn, attnq, c_attn, smoutf);

    // v transpose -> [B, H, S]
    {
        dim3 grid(HH / 32, SS / 32, BB);
        transpose8<<<grid, dim3(32, 8)>>>(v, vT);
    }

    // attn_out = attn_q @ v : NT with vT, [2048,1024], K=2048
    {
        dim3 grid(HH / BN, SS / BM, BB);
        gemm_s8_nt<<<grid, blk>>>(attnq, vT, ao, SS, HH, SS,
                                  (long long)SS * SS, (long long)HH * SS,
                                  (long long)SS * HH,
                                  c_ao, 1.0f, nullptr, 0, 0.0f);
    }

    // out = attn_out @ w_o^T, requant then dequant, FLOAT32 out : [8192,1024]
    {
        dim3 grid(HH / BN, (BB * SS) / BM, 1);
        gemm_s8_nt<<<grid, blk>>>(ao, wo, d_out, BB * SS, HH, HH, 0, 0, 0,
                                  c_out, 1.0f, nullptr, 1, deq);
    }
}

// round 16
// speedup vs baseline: 1.4548x; 1.4548x over previous
#include <cuda_runtime.h>
#include <cuda_bf16.h>
#include <cstdint>

#define BB 4
#define SS 2048
#define DD 1024
#define HH 1024

// Scratch (device globals; no allocation allowed)
__device__ int8_t g_x [(size_t)BB * SS * DD];
__device__ int8_t g_wq[(size_t)HH * DD];
__device__ int8_t g_wk[(size_t)HH * DD];
__device__ int8_t g_wv[(size_t)HH * DD];
__device__ int8_t g_wo[(size_t)HH * HH];
__device__ int8_t g_q[(size_t)BB * SS * HH];
__device__ int8_t g_k[(size_t)BB * SS * HH];
__device__ int8_t g_v[(size_t)BB * SS * HH];
__device__ int8_t g_vT[(size_t)BB * SS * HH];
__device__ int8_t g_attn[(size_t)BB * SS * SS];
__device__ int8_t g_attnq[(size_t)BB * SS * SS];
__device__ int8_t g_ao[(size_t)BB * SS * HH];

// ----------------------------------------------------------------------------
// Fused pack: all five int32-materialized tensors -> int8 scratch, one launch.
//   x: 2,097,152 char4 ; each weight: 262,144 char4
// ----------------------------------------------------------------------------
#define X4  2097152LL
#define W4  262144LL

__global__ void __launch_bounds__(256)
pack_all(const int4* __restrict__ x, const int4* __restrict__ w0,
         const int4* __restrict__ w1, const int4* __restrict__ w2,
         const int4* __restrict__ w3,
         int8_t* __restrict__ xd, int8_t* __restrict__ d0,
         int8_t* __restrict__ d1, int8_t* __restrict__ d2,
         int8_t* __restrict__ d3)
{
    long long i = (long long)blockIdx.x * blockDim.x + threadIdx.x;
    const int4* src; int8_t* dst; long long off;
    if (i < X4) { src = x; dst = xd; off = i; }
    else {
        long long j = i - X4;
        int k = (int)(j >> 18);          // /262144
        off = j & (W4 - 1);
        src = (k == 0) ? w0 : (k == 1) ? w1 : (k == 2) ? w2 : w3;
        dst = (k == 0) ? d0 : (k == 1) ? d1 : (k == 2) ? d2 : d3;
    }
    int4 v = src[off];
    char4 w;
    w.x = (char)v.x; w.y = (char)v.y; w.z = (char)v.z; w.w = (char)v.w;
    ((char4*)dst)[off] = w;
}

// ----------------------------------------------------------------------------
// PTX helpers
// ----------------------------------------------------------------------------
__device__ __forceinline__ void cpasync16(uint32_t saddr, const void* gaddr) {
    asm volatile("cp.async.cg.shared.global [%0], [%1], 16;\n"
                 :: "r"(saddr), "l"(gaddr) : "memory");
}
__device__ __forceinline__ void ldsm4(uint32_t& r0, uint32_t& r1, uint32_t& r2,
                                      uint32_t& r3, uint32_t addr) {
    asm volatile("ldmatrix.sync.aligned.m8n8.x4.shared.b16 {%0,%1,%2,%3}, [%4];\n"
                 : "=r"(r0), "=r"(r1), "=r"(r2), "=r"(r3) : "r"(addr));
}
__device__ __forceinline__ void mma_s8(int* c, uint32_t a0, uint32_t a1,
                                       uint32_t a2, uint32_t a3,
                                       uint32_t b0, uint32_t b1) {
    asm volatile(
        "mma.sync.aligned.m16n8k32.row.col.s32.s8.s8.s32 "
        "{%0,%1,%2,%3}, {%4,%5,%6,%7}, {%8,%9}, {%0,%1,%2,%3};\n"
        : "+r"(c[0]), "+r"(c[1]), "+r"(c[2]), "+r"(c[3])
        : "r"(a0), "r"(a1), "r"(a2), "r"(a3), "r"(b0), "r"(b1));
}
__device__ __forceinline__ int quant8(int acc, float s) {
    float f = rintf((float)acc * s);
    f = fminf(fmaxf(f, -128.0f), 127.0f);
    return (int)f;
}

// ----------------------------------------------------------------------------
// GEMM core: 128x256x64 tile, 8 warps (2x4), 64x64 warp tile, 3-stage cp.async
//   C[m,n] = sum_k A[m,k]*B[n,k]; requant epilogue (epi0: int8, epi1: f32)
// ----------------------------------------------------------------------------
#define BM 128
#define BN 256
#define BK 64
#define NSTAGE 3
#define STAGE_BYTES ((BM + BN) * BK)   // 24576
#define GEMM_SMEM (NSTAGE * STAGE_BYTES)

__device__ __forceinline__ void gemm_core(
    const int8_t* __restrict__ Ab, const int8_t* __restrict__ Bb,
    void* __restrict__ Cb, int N, int K, float s, int epi, float deq,
    char* smem)
{
    const int tid  = threadIdx.x;
    const int lane = tid & 31;
    const int wid  = tid >> 5;
    const int wm   = wid & 1;     // 2 warps over M (64 each)
    const int wn   = wid >> 1;    // 4 warps over N (64 each)

    uint32_t sbase = (uint32_t)__cvta_generic_to_shared(smem);
    const int ntile = K / BK;

    auto issue = [&](int kt, int stage) {
        uint32_t sa = sbase + stage * STAGE_BYTES;
        uint32_t sb = sa + BM * BK;
        #pragma unroll
        for (int i = 0; i < 2; i++) {                 // A: 512 chunks
            int c  = tid + i * 256;
            int r  = c >> 2;
            int ch = c & 3;
            uint32_t off = r * 64 + ((ch ^ ((r >> 1) & 3)) << 4);
            cpasync16(sa + off, Ab + (long long)r * K + (long long)kt * 64 + ch * 16);
        }
        #pragma unroll
        for (int i = 0; i < 4; i++) {                 // B: 1024 chunks
            int c  = tid + i * 256;
            int r  = c >> 2;
            int ch = c & 3;
            uint32_t off = r * 64 + ((ch ^ ((r >> 1) & 3)) << 4);
            cpasync16(sb + off, Bb + (long long)r * K + (long long)kt * 64 + ch * 16);
        }
        asm volatile("cp.async.commit_group;\n" ::: "memory");
    };

    int acc[4][8][4];
    #pragma unroll
    for (int a = 0; a < 4; a++)
        #pragma unroll
        for (int b = 0; b < 8; b++)
            #pragma unroll
            for (int c = 0; c < 4; c++) acc[a][b][c] = 0;

    issue(0, 0);
    issue(1, 1);

    int stage = 0;
    for (int t = 0; t < ntile; t++) {
        if (t + 1 < ntile)
            asm volatile("cp.async.wait_group 1;\n" ::: "memory");
        else
            asm volatile("cp.async.wait_group 0;\n" ::: "memory");
        __syncthreads();   // stage t visible to all; all warps done with t-1

        if (t + 2 < ntile) {
            int ns = stage + 2; if (ns >= NSTAGE) ns -= NSTAGE;
            issue(t + 2, ns);
        }

        uint32_t sa = sbase + stage * STAGE_BYTES;
        uint32_t sb = sa + BM * BK;

        #pragma unroll
        for (int ks = 0; ks < 2; ks++) {
            uint32_t afr[4][4], bfr[8][2];
            #pragma unroll
            for (int mi = 0; mi < 4; mi++) {
                int r  = wm * 64 + mi * 16 + (lane & 7) + ((lane >> 3) & 1) * 8;
                int ch = ks * 2 + (lane >> 4);
                ldsm4(afr[mi][0], afr[mi][1], afr[mi][2], afr[mi][3],
                      sa + r * 64 + ((ch ^ ((r >> 1) & 3)) << 4));
            }
            #pragma unroll
            for (int jp = 0; jp < 4; jp++) {
                int r  = wn * 64 + jp * 16 + (lane & 7) + ((lane >> 4) << 3);
                int ch = ks * 2 + ((lane >> 3) & 1);
                uint32_t m0, m1, m2, m3;
                ldsm4(m0, m1, m2, m3,
                      sb + r * 64 + ((ch ^ ((r >> 1) & 3)) << 4));
                bfr[2 * jp][0] = m0;     bfr[2 * jp][1] = m1;
                bfr[2 * jp + 1][0] = m2; bfr[2 * jp + 1][1] = m3;
            }
            #pragma unroll
            for (int mi = 0; mi < 4; mi++)
                #pragma unroll
                for (int ni = 0; ni < 8; ni++)
                    mma_s8(acc[mi][ni], afr[mi][0], afr[mi][1], afr[mi][2],
                           afr[mi][3], bfr[ni][0], bfr[ni][1]);
        }

        if (++stage >= NSTAGE) stage -= NSTAGE;
    }

    const int rowb = blockIdx.y * BM + wm * 64;
    const int colb = blockIdx.x * BN + wn * 64;

    if (epi == 0) {
        int8_t* Co = (int8_t*)Cb;
        #pragma unroll
        for (int mi = 0; mi < 4; mi++)
            #pragma unroll
            for (int ni = 0; ni < 8; ni++) {
                int r = rowb + mi * 16 + (lane >> 2);
                int c = colb + ni * 8 + (lane & 3) * 2;
                #pragma unroll
                for (int h = 0; h < 2; h++) {
                    int rr = r + h * 8;
                    char2 w;
                    w.x = (char)quant8(acc[mi][ni][2 * h], s);
                    w.y = (char)quant8(acc[mi][ni][2 * h + 1], s);
                    *(char2*)(Co + (size_t)rr * N + c) = w;
                }
            }
    } else {
        float* Co = (float*)Cb;
        #pragma unroll
        for (int mi = 0; mi < 4; mi++)
            #pragma unroll
            for (int ni = 0; ni < 8; ni++) {
                int r = rowb + mi * 16 + (lane >> 2);
                int c = colb + ni * 8 + (lane & 3) * 2;
                #pragma unroll
                for (int h = 0; h < 2; h++) {
                    int rr = r + h * 8;
                    float2 w;
                    w.x = __bfloat162float(__float2bfloat16(
                              (float)quant8(acc[mi][ni][2 * h], s) * deq));
                    w.y = __bfloat162float(__float2bfloat16(
                              (float)quant8(acc[mi][ni][2 * h + 1], s) * deq));
                    *(float2*)(Co + (size_t)rr * N + c) = w;
                }
            }
    }
}

// Fused QKV: z = 0(Q) / 1(K) / 2(V); A = x shared
__global__ void __launch_bounds__(256)
gemm_qkv(const int8_t* __restrict__ A,
         const int8_t* __restrict__ w0, const int8_t* __restrict__ w1,
         const int8_t* __restrict__ w2,
         int8_t* __restrict__ o0, int8_t* __restrict__ o1,
         int8_t* __restrict__ o2,
         const float* __restrict__ sxp)
{
    extern __shared__ char smem[];
    const int z = blockIdx.z;
    const int8_t* B = (z == 0) ? w0 : (z == 1) ? w1 : w2;
    int8_t* O       = (z == 0) ? o0 : (z == 1) ? o1 : o2;
    const float cA  = (z == 2) ? 0.034f : 0.0011f;
    const float cB  = (z == 2) ? 0.74f  : 0.2f;
    float s = __ldg(sxp) * cA / cB;

    const int8_t* Ab = A + (long long)blockIdx.y * BM * DD;
    const int8_t* Bb = B + (long long)blockIdx.x * BN * DD;
    gemm_core(Ab, Bb, O, HH, DD, s, 0, 0.0f, smem);
}

// Batched GEMM (z = batch via strides); sC in OUTPUT ELEMENTS
__global__ void __launch_bounds__(256)
gemm_bat(const int8_t* __restrict__ A, const int8_t* __restrict__ B,
         void* __restrict__ C, int N, int K,
         long long sA, long long sB, long long sC,
         float s, int epi, float deq)
{
    extern __shared__ char smem[];
    const long long z = blockIdx.z;
    const int8_t* Ab = A + z * sA + (long long)blockIdx.y * BM * K;
    const int8_t* Bb = B + z * sB + (long long)blockIdx.x * BN * K;
    void* Cz = epi ? (void*)((float*)C + z * sC)
                   : (void*)((int8_t*)C + z * sC);
    gemm_core(Ab, Bb, Cz, N, K, s, epi, deq, smem);
}

// ----------------------------------------------------------------------------
// Softmax + requant over rows of [B*S, S=2048] int8 logits
// ----------------------------------------------------------------------------
__global__ void __launch_bounds__(256)
softmax_rq(const int8_t* __restrict__ a, int8_t* __restrict__ o,
           float scale, float sm_out)
{
    __shared__ float redm[8];
    __shared__ float reds[8];

    const long long row = blockIdx.x;
    const int tid = threadIdx.x;
    const int wid = tid >> 5;

    int2 d = ((const int2*)(a + row * SS))[tid];
    signed char* p = (signed char*)&d;

    float v[8];
    float m = -1e30f;
    #pragma unroll
    for (int i = 0; i < 8; i++) {
        v[i] = (float)p[i] * scale;
        m = fmaxf(m, v[i]);
    }
    #pragma unroll
    for (int s2 = 16; s2; s2 >>= 1) m = fmaxf(m, __shfl_xor_sync(~0u, m, s2));
    if ((tid & 31) == 0) redm[wid] = m;
    __syncthreads();
    if (tid < 32) {
        float t = (tid < 8) ? redm[tid] : -1e30f;
        #pragma unroll
        for (int s2 = 4; s2; s2 >>= 1) t = fmaxf(t, __shfl_xor_sync(~0u, t, s2));
        if (tid == 0) redm[0] = t;
    }
    __syncthreads();
    m = redm[0];

    float e[8];
    float sum = 0.0f;
    #pragma unroll
    for (int i = 0; i < 8; i++) {
        e[i] = expf(v[i] - m);
        sum += e[i];
    }
    #pragma unroll
    for (int s2 = 16; s2; s2 >>= 1) sum += __shfl_xor_sync(~0u, sum, s2);
    if ((tid & 31) == 0) reds[wid] = sum;
    __syncthreads();
    if (tid < 32) {
        float t = (tid < 8) ? reds[tid] : 0.0f;
        #pragma unroll
        for (int s2 = 4; s2; s2 >>= 1) t += __shfl_xor_sync(~0u, t, s2);
        if (tid == 0) reds[0] = t;
    }
    __syncthreads();
    sum = reds[0];

    int2 out;
    signed char* po = (signed char*)&out;
    #pragma unroll
    for (int i = 0; i < 8; i++) {
        float pr = e[i] / sum;
        float f = rintf(pr / sm_out);
        f = fminf(fmaxf(f, -128.0f), 127.0f);
        po[i] = (signed char)(int)f;
    }
    ((int2*)(o + row * SS))[tid] = out;
}

// ----------------------------------------------------------------------------
// int8 transpose per batch:  out[b][h][s] = in[b][s][h]
// ----------------------------------------------------------------------------
__global__ void __launch_bounds__(256)
transpose8(const int8_t* __restrict__ in, int8_t* __restrict__ out)
{
    __shared__ char tile[32][33];
    const long long b = blockIdx.z;
    const int x0 = blockIdx.x * 32;  // H
    const int y0 = blockIdx.y * 32;  // S
    const int8_t* ib = in + b * (long long)SS * HH;
    int8_t* ob = out + b * (long long)HH * SS;

    for (int i = threadIdx.y; i < 32; i += 8)
        tile[i][threadIdx.x] = ib[(size_t)(y0 + i) * HH + x0 + threadIdx.x];
    __syncthreads();
    for (int i = threadIdx.y; i < 32; i += 8)
        ob[(size_t)(x0 + i) * SS + y0 + threadIdx.x] = tile[threadIdx.x][i];
}

// ----------------------------------------------------------------------------
// Launch
// ----------------------------------------------------------------------------
extern "C" void kernel_launch(void* const* d_in, const int* in_sizes, int n_in,
                              void* d_out, int out_size)
{
    const void* x_raw = nullptr;
    const void* w_raw[4] = {nullptr, nullptr, nullptr, nullptr};
    const float* sx = nullptr;
    int nw = 0;
    for (int i = 0; i < n_in; i++) {
        long long sz = in_sizes[i];
        if (sz == (long long)BB * SS * DD)       x_raw = d_in[i];
        else if (sz == (long long)HH * DD) {     if (nw < 4) w_raw[nw++] = d_in[i]; }
        else if (sz == 1)                        sx = (const float*)d_in[i];
    }
    if (!x_raw || !sx || nw != 4) {
        x_raw = d_in[0]; sx = (const float*)d_in[1];
        w_raw[0] = d_in[2]; w_raw[1] = d_in[3]; w_raw[2] = d_in[4]; w_raw[3] = d_in[5];
    }

    static int8_t *x = nullptr, *wq, *wk, *wv, *wo,
                  *q, *k, *v, *vT, *attn, *attnq, *ao;
    if (!x) {  // first call is the uncaptured correctness run
        cudaGetSymbolAddress((void**)&x,  g_x);
        cudaGetSymbolAddress((void**)&wq, g_wq);
        cudaGetSymbolAddress((void**)&wk, g_wk);
        cudaGetSymbolAddress((void**)&wv, g_wv);
        cudaGetSymbolAddress((void**)&wo, g_wo);
        cudaGetSymbolAddress((void**)&q, g_q);
        cudaGetSymbolAddress((void**)&k, g_k);
        cudaGetSymbolAddress((void**)&v, g_v);
        cudaGetSymbolAddress((void**)&vT, g_vT);
        cudaGetSymbolAddress((void**)&attn, g_attn);
        cudaGetSymbolAddress((void**)&attnq, g_attnq);
        cudaGetSymbolAddress((void**)&ao, g_ao);
        cudaFuncSetAttribute(gemm_qkv,
            cudaFuncAttributeMaxDynamicSharedMemorySize, GEMM_SMEM);
        cudaFuncSetAttribute(gemm_bat,
            cudaFuncAttributeMaxDynamicSharedMemorySize, GEMM_SMEM);
    }

    const float c_attn = (float)(0.2 * 0.2);                              // OS_Q*OS_K
    const float c_ao   = (float)((1.0 / 127.0) * 0.74);                   // SM_OUT*OS_V
    const float c_out  = (float)((1.0 / 127.0) * 0.74 * 0.01 / 0.046);    // ... *WS_O/OS_O
    const float smoutf = (float)(1.0 / 127.0);
    const float deq    = 0.046f;                                          // OS_O

    // 1. fused pack (int32 -> int8), one launch
    {
        long long tot4 = X4 + 4 * W4;                 // 3,145,728 char4
        pack_all<<<(unsigned)(tot4 / 256), 256>>>(
            (const int4*)x_raw, (const int4*)w_raw[0], (const int4*)w_raw[1],
            (const int4*)w_raw[2], (const int4*)w_raw[3],
            x, wq, wk, wv, wo);
    }

    // 2. fused QKV projections: z in {Q,K,V}; [8192,1024] each
    {
        dim3 grid(HH / BN, (BB * SS) / BM, 3);
        gemm_qkv<<<grid, 256, GEMM_SMEM>>>(x, wq, wk, wv, q, k, v, sx);
    }

    // 3. attn = q @ k^T per batch : [2048,2048], K=1024
    {
        dim3 grid(SS / BN, SS / BM, BB);
        gemm_bat<<<grid, 256, GEMM_SMEM>>>(q, k, attn, SS, HH,
                                           (long long)SS * HH, (long long)SS * HH,
                                           (long long)SS * SS,
                                           c_attn, 0, 0.0f);
    }

    // 4. softmax + requant
    softmax_rq<<<BB * SS, 256>>>(attn, attnq, c_attn, smoutf);

    // 5. v transpose -> [B, H, S]
    {
        dim3 grid(HH / 32, SS / 32, BB);
        transpose8<<<grid, dim3(32, 8)>>>(v, vT);
    }

    // 6. attn_out = attn_q @ v : NT with vT, [2048,1024], K=2048
    {
        dim3 grid(HH / BN, SS / BM, BB);
        gemm_bat<<<grid, 256, GEMM_SMEM>>>(attnq, vT, ao, HH, SS,
                                           (long long)SS * SS, (long long)HH * SS,
                                           (long long)SS * HH,
                                           c_ao, 0, 0.0f);
    }

    // 7. out = attn_out @ w_o^T, f32 out (bf16-rounded values) : [8192,1024]
    {
        dim3 grid(HH / BN, (BB * SS) / BM, 1);
        gemm_bat<<<grid, 256, GEMM_SMEM>>>(ao, wo, d_out, HH, HH,
                                           0, 0, 0, c_out, 1, deq);
    }
}